// round 3
// baseline (speedup 1.0000x reference)
#include <cuda_runtime.h>
#include <cuda_bf16.h>
#include <cstdint>

#define S_LEN 8192
#define HID   1024
#define NH    16
#define DH    64
#define WIN   128
#define CHUNK 128
#define KEYS  384
#define ROWE  72            // bf16 elems per padded row (144 B)
#define ROWB  (ROWE * 2)
#define PLANE (KEYS * ROWB)      // 55296 B
#define SMEM_TOTAL (4 * PLANE)   // 221184 B

// ---------- PTX wrappers ----------
__device__ __forceinline__ void ldsm4(uint32_t addr, uint32_t r[4]) {
    asm volatile("ldmatrix.sync.aligned.m8n8.x4.shared.b16 {%0,%1,%2,%3}, [%4];"
        : "=r"(r[0]), "=r"(r[1]), "=r"(r[2]), "=r"(r[3]) : "r"(addr));
}
__device__ __forceinline__ void ldsm4t(uint32_t addr, uint32_t r[4]) {
    asm volatile("ldmatrix.sync.aligned.m8n8.x4.trans.shared.b16 {%0,%1,%2,%3}, [%4];"
        : "=r"(r[0]), "=r"(r[1]), "=r"(r[2]), "=r"(r[3]) : "r"(addr));
}
__device__ __forceinline__ void mma16816(float* c, const uint32_t* a, uint32_t b0, uint32_t b1) {
    asm volatile("mma.sync.aligned.m16n8k16.row.col.f32.bf16.bf16.f32 "
        "{%0,%1,%2,%3}, {%4,%5,%6,%7}, {%8,%9}, {%0,%1,%2,%3};"
        : "+f"(c[0]), "+f"(c[1]), "+f"(c[2]), "+f"(c[3])
        : "r"(a[0]), "r"(a[1]), "r"(a[2]), "r"(a[3]), "r"(b0), "r"(b1));
}
// split two floats into packed-bf16 hi word + residual lo word
__device__ __forceinline__ void split_pack(float x0, float x1, uint32_t& hi, uint32_t& lo) {
    uint32_t h;
    asm("cvt.rn.bf16x2.f32 %0, %1, %2;" : "=r"(h) : "f"(x1), "f"(x0));
    float f0 = __uint_as_float(h << 16);
    float f1 = __uint_as_float(h & 0xffff0000u);
    uint32_t l2;
    asm("cvt.rn.bf16x2.f32 %0, %1, %2;" : "=r"(l2) : "f"(x1 - f1), "f"(x0 - f0));
    hi = h; lo = l2;
}

extern __shared__ char sm[];

__global__ __launch_bounds__(256, 1)
void swa_mma_kernel(const float* __restrict__ Q, const float* __restrict__ K,
                    const float* __restrict__ V, float* __restrict__ O) {
    const int tid  = threadIdx.x;
    const int warp = tid >> 5;
    const int lane = tid & 31;
    const int g    = lane >> 2;
    const int tt   = lane & 3;
    const int mm   = lane >> 3;
    const int lm7  = lane & 7;

    const int c = blockIdx.x, h = blockIdx.y, b = blockIdx.z;
    const int cb = c * CHUNK;
    const int base = cb - WIN;               // absolute key of window start

    const uint32_t SB   = (uint32_t)__cvta_generic_to_shared(sm);
    const uint32_t K_HI = SB;
    const uint32_t K_LO = SB + PLANE;
    const uint32_t V_HI = SB + 2 * PLANE;
    const uint32_t V_LO = SB + 3 * PLANE;

    // staging addressing for this thread (2 segments per 32-key tile)
    const int j0   = tid;                 // seg 0: j0,  seg 1: j0+256
    const int srowA = j0 >> 4;            // 0..15
    const int srowB = (j0 + 256) >> 4;    // 16..31
    const int sc4   = (j0 & 15) * 4;

    // ---------------- Q fragments: direct gmem -> registers (split bf16) ----------------
    uint32_t aqh[4][4], aql[4][4];
    {
        const int qrow = cb + warp * 16 + g;
        const float* qp = Q + ((size_t)(b * S_LEN + qrow) * HID) + h * DH;
        #pragma unroll
        for (int kg = 0; kg < 4; kg++) {
            const int col0 = kg * 16 + 2 * tt;
            float2 x0 = *(const float2*)(qp + col0);
            float2 x1 = *(const float2*)(qp + 8 * HID + col0);
            float2 x2 = *(const float2*)(qp + col0 + 8);
            float2 x3 = *(const float2*)(qp + 8 * HID + col0 + 8);
            split_pack(x0.x, x0.y, aqh[kg][0], aql[kg][0]);
            split_pack(x1.x, x1.y, aqh[kg][1], aql[kg][1]);
            split_pack(x2.x, x2.y, aqh[kg][2], aql[kg][2]);
            split_pack(x3.x, x3.y, aqh[kg][3], aql[kg][3]);
        }
    }

    // ---------------- Stage tiles 0..3 (keys base .. base+127) ----------------
    {
        #pragma unroll
        for (int it = 0; it < 8; it++) {
            int j   = tid + it * 256;
            int row = j >> 4;                 // 0..127
            int c4  = (j & 15) * 4;
            int key = base + row;
            float4 k4 = make_float4(0.f, 0.f, 0.f, 0.f), v4 = k4;
            if (key >= 0 && key < S_LEN) {
                size_t off = ((size_t)(b * S_LEN + key) * HID) + h * DH + c4;
                k4 = *(const float4*)(K + off);
                v4 = *(const float4*)(V + off);
            }
            int so = row * ROWB + c4 * 2;
            uint32_t h0, l0, h1, l1;
            split_pack(k4.x, k4.y, h0, l0);
            split_pack(k4.z, k4.w, h1, l1);
            *(uint32_t*)(sm + so)             = h0;
            *(uint32_t*)(sm + so + 4)         = h1;
            *(uint32_t*)(sm + PLANE + so)     = l0;
            *(uint32_t*)(sm + PLANE + so + 4) = l1;
            split_pack(v4.x, v4.y, h0, l0);
            split_pack(v4.z, v4.w, h1, l1);
            *(uint32_t*)(sm + 2 * PLANE + so)     = h0;
            *(uint32_t*)(sm + 2 * PLANE + so + 4) = h1;
            *(uint32_t*)(sm + 3 * PLANE + so)     = l0;
            *(uint32_t*)(sm + 3 * PLANE + so + 4) = l1;
        }
    }
    __syncthreads();

    // ---------------- Main loop: 9 tiles per warp, staging tile i+4 in-loop ----------------
    float of[8][4];
    #pragma unroll
    for (int j = 0; j < 8; j++)
        #pragma unroll
        for (int r = 0; r < 4; r++) of[j][r] = 0.f;
    float rs[2] = {0.f, 0.f};

    const int t0  = warp >> 1;
    const int qa0 = cb + warp * 16;

    #pragma unroll 1
    for (int i = 0; i < 9; i++) {
        const bool st    = (i < 8);
        const int  srow0 = (i + 4) * 32;                // tile being staged
        const int  keyA  = base + srow0 + srowA;
        const int  keyB  = base + srow0 + srowB;
        const bool okA   = st && (keyA >= 0) && (keyA < S_LEN);
        const bool okB   = st && (keyB >= 0) && (keyB < S_LEN);
        const size_t offA = ((size_t)(b * S_LEN + keyA) * HID) + h * DH + sc4;
        const size_t offB = ((size_t)(b * S_LEN + keyB) * HID) + h * DH + sc4;

        // issue K staging loads early — latency hides under QK MMAs
        float4 kr0 = make_float4(0.f,0.f,0.f,0.f), kr1 = kr0;
        if (okA) kr0 = *(const float4*)(K + offA);
        if (okB) kr1 = *(const float4*)(K + offB);

        const int kloc0 = (t0 + i) * 32;
        const int kabs  = base + kloc0;

        // ---- S = Q K^T (QhKh + QlKh + QhKl) ----
        float sacc[4][4];
        #pragma unroll
        for (int j = 0; j < 4; j++)
            #pragma unroll
            for (int r = 0; r < 4; r++) sacc[j][r] = 0.f;

        #pragma unroll
        for (int kg = 0; kg < 4; kg++) {
            #pragma unroll
            for (int np = 0; np < 2; np++) {
                int keyrow = kloc0 + np * 16 + (mm >> 1) * 8 + lm7;
                int dim    = kg * 16 + (mm & 1) * 8;
                uint32_t off = (uint32_t)(keyrow * ROWB + dim * 2);
                uint32_t kbh[4], kbl[4];
                ldsm4(K_HI + off, kbh);
                ldsm4(K_LO + off, kbl);
                mma16816(sacc[2 * np],     aqh[kg], kbh[0], kbh[1]);
                mma16816(sacc[2 * np],     aql[kg], kbh[0], kbh[1]);
                mma16816(sacc[2 * np],     aqh[kg], kbl[0], kbl[1]);
                mma16816(sacc[2 * np + 1], aqh[kg], kbh[2], kbh[3]);
                mma16816(sacc[2 * np + 1], aql[kg], kbh[2], kbh[3]);
                mma16816(sacc[2 * np + 1], aqh[kg], kbl[2], kbl[3]);
            }
        }

        // ---- softmax (no-max; masked on edge tiles) ----
        const bool edge = (i == 0) | (i == 8) | (kabs < 0) | (kabs + 31 >= S_LEN);
        if (edge) {
            #pragma unroll
            for (int j = 0; j < 4; j++) {
                #pragma unroll
                for (int r = 0; r < 4; r++) {
                    int key  = kabs + 8 * j + 2 * tt + (r & 1);
                    int qrow = qa0 + g + ((r >> 1) << 3);
                    bool valid = (key >= 0) && (key < S_LEN) &&
                                 (key >= qrow - WIN) && (key <= qrow + WIN);
                    float e = valid ? __expf(sacc[j][r]) : 0.f;
                    sacc[j][r] = e;
                    rs[r >> 1] += e;
                }
            }
        } else {
            #pragma unroll
            for (int j = 0; j < 4; j++) {
                #pragma unroll
                for (int r = 0; r < 4; r++) {
                    float e = __expf(sacc[j][r]);
                    sacc[j][r] = e;
                    rs[r >> 1] += e;
                }
            }
        }

        // ---- store staged K, issue V staging loads ----
        float4 vr0 = make_float4(0.f,0.f,0.f,0.f), vr1 = vr0;
        if (st) {
            uint32_t h0, l0, h1, l1;
            int soA = (srow0 + srowA) * ROWB + sc4 * 2;
            int soB = (srow0 + srowB) * ROWB + sc4 * 2;
            split_pack(kr0.x, kr0.y, h0, l0);
            split_pack(kr0.z, kr0.w, h1, l1);
            *(uint32_t*)(sm + soA)             = h0;
            *(uint32_t*)(sm + soA + 4)         = h1;
            *(uint32_t*)(sm + PLANE + soA)     = l0;
            *(uint32_t*)(sm + PLANE + soA + 4) = l1;
            split_pack(kr1.x, kr1.y, h0, l0);
            split_pack(kr1.z, kr1.w, h1, l1);
            *(uint32_t*)(sm + soB)             = h0;
            *(uint32_t*)(sm + soB + 4)         = h1;
            *(uint32_t*)(sm + PLANE + soB)     = l0;
            *(uint32_t*)(sm + PLANE + soB + 4) = l1;
            if (okA) vr0 = *(const float4*)(V + offA);
            if (okB) vr1 = *(const float4*)(V + offB);
        }

        // ---- P fragments (accumulator layout == A layout) ----
        uint32_t pah[2][4], pal[2][4];
        #pragma unroll
        for (int kg = 0; kg < 2; kg++) {
            split_pack(sacc[2 * kg][0],     sacc[2 * kg][1],     pah[kg][0], pal[kg][0]);
            split_pack(sacc[2 * kg][2],     sacc[2 * kg][3],     pah[kg][1], pal[kg][1]);
            split_pack(sacc[2 * kg + 1][0], sacc[2 * kg + 1][1], pah[kg][2], pal[kg][2]);
            split_pack(sacc[2 * kg + 1][2], sacc[2 * kg + 1][3], pah[kg][3], pal[kg][3]);
        }

        // ---- O += P V (PhVh + PlVh + PhVl) ----
        #pragma unroll
        for (int kg = 0; kg < 2; kg++) {
            #pragma unroll
            for (int jp = 0; jp < 4; jp++) {
                int keyrow = kloc0 + kg * 16 + (mm & 1) * 8 + lm7;
                int dim    = (jp * 2 + (mm >> 1)) * 8;
                uint32_t off = (uint32_t)(keyrow * ROWB + dim * 2);
                uint32_t vbh[4], vbl[4];
                ldsm4t(V_HI + off, vbh);
                ldsm4t(V_LO + off, vbl);
                mma16816(of[2 * jp],     pah[kg], vbh[0], vbh[1]);
                mma16816(of[2 * jp],     pal[kg], vbh[0], vbh[1]);
                mma16816(of[2 * jp],     pah[kg], vbl[0], vbl[1]);
                mma16816(of[2 * jp + 1], pah[kg], vbh[2], vbh[3]);
                mma16816(of[2 * jp + 1], pal[kg], vbh[2], vbh[3]);
                mma16816(of[2 * jp + 1], pah[kg], vbl[2], vbl[3]);
            }
        }

        // ---- store staged V ----
        if (st) {
            uint32_t h0, l0, h1, l1;
            int soA = (srow0 + srowA) * ROWB + sc4 * 2;
            int soB = (srow0 + srowB) * ROWB + sc4 * 2;
            split_pack(vr0.x, vr0.y, h0, l0);
            split_pack(vr0.z, vr0.w, h1, l1);
            *(uint32_t*)(sm + 2 * PLANE + soA)     = h0;
            *(uint32_t*)(sm + 2 * PLANE + soA + 4) = h1;
            *(uint32_t*)(sm + 3 * PLANE + soA)     = l0;
            *(uint32_t*)(sm + 3 * PLANE + soA + 4) = l1;
            split_pack(vr1.x, vr1.y, h0, l0);
            split_pack(vr1.z, vr1.w, h1, l1);
            *(uint32_t*)(sm + 2 * PLANE + soB)     = h0;
            *(uint32_t*)(sm + 2 * PLANE + soB + 4) = h1;
            *(uint32_t*)(sm + 3 * PLANE + soB)     = l0;
            *(uint32_t*)(sm + 3 * PLANE + soB + 4) = l1;
        }
        __syncthreads();
    }

    // ---------------- Epilogue ----------------
    rs[0] += __shfl_xor_sync(0xffffffffu, rs[0], 1);
    rs[0] += __shfl_xor_sync(0xffffffffu, rs[0], 2);
    rs[1] += __shfl_xor_sync(0xffffffffu, rs[1], 1);
    rs[1] += __shfl_xor_sync(0xffffffffu, rs[1], 2);
    const float inv_lo = 1.f / rs[0];
    const float inv_hi = 1.f / rs[1];

    const int q_lo = qa0 + g;
    const int q_hi = q_lo + 8;
    #pragma unroll
    for (int j = 0; j < 8; j++) {
        int col = h * DH + 8 * j + 2 * tt;
        size_t off_lo = ((size_t)(b * S_LEN + q_lo) * HID) + col;
        size_t off_hi = ((size_t)(b * S_LEN + q_hi) * HID) + col;
        *(float2*)(O + off_lo) = make_float2(of[j][0] * inv_lo, of[j][1] * inv_lo);
        *(float2*)(O + off_hi) = make_float2(of[j][2] * inv_hi, of[j][3] * inv_hi);
    }
}

extern "C" void kernel_launch(void* const* d_in, const int* in_sizes, int n_in,
                              void* d_out, int out_size) {
    (void)n_in; (void)out_size;
    const float* Q = (const float*)d_in[0];
    const float* K = (const float*)d_in[1];
    const float* V = (const float*)d_in[2];
    float* O = (float*)d_out;

    int B = in_sizes[0] / (S_LEN * HID);
    cudaFuncSetAttribute(swa_mma_kernel,
                         cudaFuncAttributeMaxDynamicSharedMemorySize, SMEM_TOTAL);
    dim3 grid(S_LEN / CHUNK, NH, B);
    swa_mma_kernel<<<grid, 256, SMEM_TOTAL>>>(Q, K, V, O);
}

// round 5
// speedup vs baseline: 1.1801x; 1.1801x over previous
#include <cuda_runtime.h>
#include <cuda_bf16.h>
#include <cstdint>

#define S_LEN 8192
#define HID   1024
#define NH    16
#define DH    64
#define WIN   128
#define CHUNK 128
#define KEYS  384
#define ROWE  72            // bf16 elems per padded row (144 B)
#define ROWB  (ROWE * 2)
#define PLANE (KEYS * ROWB)      // 55296 B
#define SMEM_TOTAL (4 * PLANE)   // 221184 B

// ---------- PTX wrappers ----------
__device__ __forceinline__ void ldsm4(uint32_t addr, uint32_t r[4]) {
    asm volatile("ldmatrix.sync.aligned.m8n8.x4.shared.b16 {%0,%1,%2,%3}, [%4];"
        : "=r"(r[0]), "=r"(r[1]), "=r"(r[2]), "=r"(r[3]) : "r"(addr));
}
__device__ __forceinline__ void ldsm4t(uint32_t addr, uint32_t r[4]) {
    asm volatile("ldmatrix.sync.aligned.m8n8.x4.trans.shared.b16 {%0,%1,%2,%3}, [%4];"
        : "=r"(r[0]), "=r"(r[1]), "=r"(r[2]), "=r"(r[3]) : "r"(addr));
}
__device__ __forceinline__ void mma16816(float* c, const uint32_t* a, uint32_t b0, uint32_t b1) {
    asm volatile("mma.sync.aligned.m16n8k16.row.col.f32.bf16.bf16.f32 "
        "{%0,%1,%2,%3}, {%4,%5,%6,%7}, {%8,%9}, {%0,%1,%2,%3};"
        : "+f"(c[0]), "+f"(c[1]), "+f"(c[2]), "+f"(c[3])
        : "r"(a[0]), "r"(a[1]), "r"(a[2]), "r"(a[3]), "r"(b0), "r"(b1));
}
// split two floats into packed-bf16 hi word + residual lo word
__device__ __forceinline__ void split_pack(float x0, float x1, uint32_t& hi, uint32_t& lo) {
    uint32_t h;
    asm("cvt.rn.bf16x2.f32 %0, %1, %2;" : "=r"(h) : "f"(x1), "f"(x0));
    float f0 = __uint_as_float(h << 16);
    float f1 = __uint_as_float(h & 0xffff0000u);
    uint32_t l2;
    asm("cvt.rn.bf16x2.f32 %0, %1, %2;" : "=r"(l2) : "f"(x1 - f1), "f"(x0 - f0));
    hi = h; lo = l2;
}

extern __shared__ char sm[];

// ---- QK of one 32-key tile into score buffer S (zeroed here) ----
#define QK_TILE(S, TI) do {                                                     \
    const int kloc0q = (t0 + (TI)) * 32;                                        \
    _Pragma("unroll")                                                           \
    for (int j = 0; j < 4; j++)                                                 \
        _Pragma("unroll")                                                       \
        for (int r = 0; r < 4; r++) S[j][r] = 0.f;                              \
    _Pragma("unroll")                                                           \
    for (int kg = 0; kg < 4; kg++) {                                            \
        _Pragma("unroll")                                                       \
        for (int np = 0; np < 2; np++) {                                        \
            int keyrow = kloc0q + np * 16 + (mm >> 1) * 8 + lm7;                \
            int dim    = kg * 16 + (mm & 1) * 8;                                \
            uint32_t off = (uint32_t)(keyrow * ROWB + dim * 2);                 \
            uint32_t kbh[4], kbl[4];                                            \
            ldsm4(K_HI + off, kbh);                                             \
            ldsm4(K_LO + off, kbl);                                             \
            mma16816(S[2*np],   aqh[kg], kbh[0], kbh[1]);                       \
            mma16816(S[2*np],   aql[kg], kbh[0], kbh[1]);                       \
            mma16816(S[2*np],   aqh[kg], kbl[0], kbl[1]);                       \
            mma16816(S[2*np+1], aqh[kg], kbh[2], kbh[3]);                       \
            mma16816(S[2*np+1], aql[kg], kbh[2], kbh[3]);                       \
            mma16816(S[2*np+1], aqh[kg], kbl[2], kbl[3]);                       \
        }                                                                       \
    }                                                                           \
} while (0)

// ---- softmax + P pack + PV of one tile whose scores are in S ----
#define SM_PV(S, TI) do {                                                       \
    const int kloc0p = (t0 + (TI)) * 32;                                        \
    const int kabs   = base + kloc0p;                                           \
    const bool edge = ((TI) == 0) | ((TI) == 8) | (kabs < 0) | (kabs + 31 >= S_LEN); \
    if (edge) {                                                                 \
        _Pragma("unroll")                                                       \
        for (int j = 0; j < 4; j++) {                                           \
            _Pragma("unroll")                                                   \
            for (int r = 0; r < 4; r++) {                                       \
                int key  = kabs + 8 * j + 2 * tt + (r & 1);                     \
                int qrow = qa0 + g + ((r >> 1) << 3);                           \
                bool valid = (key >= 0) && (key < S_LEN) &&                     \
                             (key >= qrow - WIN) && (key <= qrow + WIN);        \
                float e = valid ? __expf(S[j][r]) : 0.f;                        \
                S[j][r] = e;                                                    \
                rs[r >> 1] += e;                                                \
            }                                                                   \
        }                                                                       \
    } else {                                                                    \
        _Pragma("unroll")                                                       \
        for (int j = 0; j < 4; j++) {                                           \
            _Pragma("unroll")                                                   \
            for (int r = 0; r < 4; r++) {                                       \
                float e = __expf(S[j][r]);                                      \
                S[j][r] = e;                                                    \
                rs[r >> 1] += e;                                                \
            }                                                                   \
        }                                                                       \
    }                                                                           \
    uint32_t pah[2][4], pal[2][4];                                              \
    _Pragma("unroll")                                                           \
    for (int kg = 0; kg < 2; kg++) {                                            \
        split_pack(S[2*kg][0],   S[2*kg][1],   pah[kg][0], pal[kg][0]);         \
        split_pack(S[2*kg][2],   S[2*kg][3],   pah[kg][1], pal[kg][1]);         \
        split_pack(S[2*kg+1][0], S[2*kg+1][1], pah[kg][2], pal[kg][2]);         \
        split_pack(S[2*kg+1][2], S[2*kg+1][3], pah[kg][3], pal[kg][3]);         \
    }                                                                           \
    _Pragma("unroll")                                                           \
    for (int kg = 0; kg < 2; kg++) {                                            \
        _Pragma("unroll")                                                       \
        for (int jp = 0; jp < 4; jp++) {                                        \
            int keyrow = kloc0p + kg * 16 + (mm & 1) * 8 + lm7;                 \
            int dim    = (jp * 2 + (mm >> 1)) * 8;                              \
            uint32_t off = (uint32_t)(keyrow * ROWB + dim * 2);                 \
            uint32_t vbh[4], vbl[4];                                            \
            ldsm4t(V_HI + off, vbh);                                            \
            ldsm4t(V_LO + off, vbl);                                            \
            mma16816(of[2*jp],   pah[kg], vbh[0], vbh[1]);                      \
            mma16816(of[2*jp],   pal[kg], vbh[0], vbh[1]);                      \
            mma16816(of[2*jp],   pah[kg], vbl[0], vbl[1]);                      \
            mma16816(of[2*jp+1], pah[kg], vbh[2], vbh[3]);                      \
            mma16816(of[2*jp+1], pal[kg], vbh[2], vbh[3]);                      \
            mma16816(of[2*jp+1], pah[kg], vbl[2], vbl[3]);                      \
        }                                                                       \
    }                                                                           \
} while (0)

__global__ __launch_bounds__(256, 1)
void swa_mma_kernel(const float* __restrict__ Q, const float* __restrict__ K,
                    const float* __restrict__ V, float* __restrict__ O) {
    const int tid  = threadIdx.x;
    const int warp = tid >> 5;
    const int lane = tid & 31;
    const int g    = lane >> 2;
    const int tt   = lane & 3;
    const int mm   = lane >> 3;
    const int lm7  = lane & 7;

    const int c = blockIdx.x, h = blockIdx.y, b = blockIdx.z;
    const int cb = c * CHUNK;
    const int base = cb - WIN;

    const uint32_t SB   = (uint32_t)__cvta_generic_to_shared(sm);
    const uint32_t K_HI = SB;
    const uint32_t K_LO = SB + PLANE;
    const uint32_t V_HI = SB + 2 * PLANE;
    const uint32_t V_LO = SB + 3 * PLANE;

    // ---------------- Q fragments: direct gmem -> registers (split bf16) ----------------
    uint32_t aqh[4][4], aql[4][4];
    {
        const int qrow = cb + warp * 16 + g;
        const float* qp = Q + ((size_t)(b * S_LEN + qrow) * HID) + h * DH;
        #pragma unroll
        for (int kg = 0; kg < 4; kg++) {
            const int col0 = kg * 16 + 2 * tt;
            float2 x0 = *(const float2*)(qp + col0);
            float2 x1 = *(const float2*)(qp + 8 * HID + col0);
            float2 x2 = *(const float2*)(qp + col0 + 8);
            float2 x3 = *(const float2*)(qp + 8 * HID + col0 + 8);
            split_pack(x0.x, x0.y, aqh[kg][0], aql[kg][0]);
            split_pack(x1.x, x1.y, aqh[kg][1], aql[kg][1]);
            split_pack(x2.x, x2.y, aqh[kg][2], aql[kg][2]);
            split_pack(x3.x, x3.y, aqh[kg][3], aql[kg][3]);
        }
    }

    // ---------------- Stage K,V (384 keys, zero-filled out of range) ----------------
    {
        #pragma unroll
        for (int it = 0; it < 24; it++) {
            int j   = tid + it * 256;
            int row = j >> 4;
            int c4  = (j & 15) * 4;
            int key = base + row;
            float4 k4 = make_float4(0.f, 0.f, 0.f, 0.f), v4 = k4;
            if (key >= 0 && key < S_LEN) {
                size_t off = ((size_t)(b * S_LEN + key) * HID) + h * DH + c4;
                k4 = *(const float4*)(K + off);
                v4 = *(const float4*)(V + off);
            }
            int so = row * ROWB + c4 * 2;
            uint32_t h0, l0, h1, l1;
            split_pack(k4.x, k4.y, h0, l0);
            split_pack(k4.z, k4.w, h1, l1);
            *(uint32_t*)(sm + so)             = h0;
            *(uint32_t*)(sm + so + 4)         = h1;
            *(uint32_t*)(sm + PLANE + so)     = l0;
            *(uint32_t*)(sm + PLANE + so + 4) = l1;
            split_pack(v4.x, v4.y, h0, l0);
            split_pack(v4.z, v4.w, h1, l1);
            *(uint32_t*)(sm + 2 * PLANE + so)     = h0;
            *(uint32_t*)(sm + 2 * PLANE + so + 4) = h1;
            *(uint32_t*)(sm + 3 * PLANE + so)     = l0;
            *(uint32_t*)(sm + 3 * PLANE + so + 4) = l1;
        }
    }
    __syncthreads();

    // ---------------- Main loop: 9 tiles per warp, QK pipelined one tile ahead ----------------
    float of[8][4];
    #pragma unroll
    for (int j = 0; j < 8; j++)
        #pragma unroll
        for (int r = 0; r < 4; r++) of[j][r] = 0.f;
    float rs[2] = {0.f, 0.f};

    const int t0  = warp >> 1;
    const int qa0 = cb + warp * 16;

    float sA[4][4], sB[4][4];
    QK_TILE(sA, 0);
    #pragma unroll 1
    for (int ii = 0; ii < 4; ii++) {
        QK_TILE(sB, 2 * ii + 1);    // next-tile scores issue before softmax+PV of current
        SM_PV(sA, 2 * ii);
        QK_TILE(sA, 2 * ii + 2);
        SM_PV(sB, 2 * ii + 1);
    }
    SM_PV(sA, 8);

    // ---------------- Epilogue ----------------
    rs[0] += __shfl_xor_sync(0xffffffffu, rs[0], 1);
    rs[0] += __shfl_xor_sync(0xffffffffu, rs[0], 2);
    rs[1] += __shfl_xor_sync(0xffffffffu, rs[1], 1);
    rs[1] += __shfl_xor_sync(0xffffffffu, rs[1], 2);
    const float inv_lo = 1.f / rs[0];
    const float inv_hi = 1.f / rs[1];

    const int q_lo = qa0 + g;
    const int q_hi = q_lo + 8;
    #pragma unroll
    for (int j = 0; j < 8; j++) {
        int col = h * DH + 8 * j + 2 * tt;
        size_t off_lo = ((size_t)(b * S_LEN + q_lo) * HID) + col;
        size_t off_hi = ((size_t)(b * S_LEN + q_hi) * HID) + col;
        *(float2*)(O + off_lo) = make_float2(of[j][0] * inv_lo, of[j][1] * inv_lo);
        *(float2*)(O + off_hi) = make_float2(of[j][2] * inv_hi, of[j][3] * inv_hi);
    }
}

extern "C" void kernel_launch(void* const* d_in, const int* in_sizes, int n_in,
                              void* d_out, int out_size) {
    (void)n_in; (void)out_size;
    const float* Q = (const float*)d_in[0];
    const float* K = (const float*)d_in[1];
    const float* V = (const float*)d_in[2];
    float* O = (float*)d_out;

    int B = in_sizes[0] / (S_LEN * HID);
    cudaFuncSetAttribute(swa_mma_kernel,
                         cudaFuncAttributeMaxDynamicSharedMemorySize, SMEM_TOTAL);
    dim3 grid(S_LEN / CHUNK, NH, B);
    swa_mma_kernel<<<grid, 256, SMEM_TOTAL>>>(Q, K, V, O);
}

// round 6
// speedup vs baseline: 1.5615x; 1.3232x over previous
#include <cuda_runtime.h>
#include <cuda_fp16.h>
#include <cstdint>

#define S_LEN 8192
#define HID   1024
#define NH    16
#define DH    64
#define WIN   128
#define CHUNK 128
#define KEYS  384
#define ROWE  72            // fp16 elems per padded row (144 B)
#define ROWB  (ROWE * 2)
#define PLANE (KEYS * ROWB)      // 55296 B
#define SMEM_TOTAL (3 * PLANE)   // 165888 B  (K_hi, K_lo, V)

// ---------- PTX wrappers ----------
__device__ __forceinline__ void ldsm4(uint32_t addr, uint32_t r[4]) {
    asm volatile("ldmatrix.sync.aligned.m8n8.x4.shared.b16 {%0,%1,%2,%3}, [%4];"
        : "=r"(r[0]), "=r"(r[1]), "=r"(r[2]), "=r"(r[3]) : "r"(addr));
}
__device__ __forceinline__ void ldsm4t(uint32_t addr, uint32_t r[4]) {
    asm volatile("ldmatrix.sync.aligned.m8n8.x4.trans.shared.b16 {%0,%1,%2,%3}, [%4];"
        : "=r"(r[0]), "=r"(r[1]), "=r"(r[2]), "=r"(r[3]) : "r"(addr));
}
__device__ __forceinline__ void mma16816h(float* c, const uint32_t* a, uint32_t b0, uint32_t b1) {
    asm volatile("mma.sync.aligned.m16n8k16.row.col.f32.f16.f16.f32 "
        "{%0,%1,%2,%3}, {%4,%5,%6,%7}, {%8,%9}, {%0,%1,%2,%3};"
        : "+f"(c[0]), "+f"(c[1]), "+f"(c[2]), "+f"(c[3])
        : "r"(a[0]), "r"(a[1]), "r"(a[2]), "r"(a[3]), "r"(b0), "r"(b1));
}
// split two floats into packed-fp16 hi word + residual lo word (x0 in low half)
__device__ __forceinline__ void split_pack_h(float x0, float x1, uint32_t& hi, uint32_t& lo) {
    __half2 h2 = __floats2half2_rn(x0, x1);
    float2  bk = __half22float2(h2);
    __half2 l2 = __floats2half2_rn(x0 - bk.x, x1 - bk.y);
    hi = *reinterpret_cast<uint32_t*>(&h2);
    lo = *reinterpret_cast<uint32_t*>(&l2);
}
__device__ __forceinline__ uint32_t pack_h(float x0, float x1) {
    __half2 h2 = __floats2half2_rn(x0, x1);
    return *reinterpret_cast<uint32_t*>(&h2);
}

extern __shared__ char sm[];

// ---- QK of one 32-key tile into score buffer S (zeroed here), fp16 3-term ----
#define QK_TILE(S, TI) do {                                                     \
    const int kloc0q = (t0 + (TI)) * 32;                                        \
    _Pragma("unroll")                                                           \
    for (int j = 0; j < 4; j++)                                                 \
        _Pragma("unroll")                                                       \
        for (int r = 0; r < 4; r++) S[j][r] = 0.f;                              \
    _Pragma("unroll")                                                           \
    for (int kg = 0; kg < 4; kg++) {                                            \
        _Pragma("unroll")                                                       \
        for (int np = 0; np < 2; np++) {                                        \
            int keyrow = kloc0q + np * 16 + (mm >> 1) * 8 + lm7;                \
            int dim    = kg * 16 + (mm & 1) * 8;                                \
            uint32_t off = (uint32_t)(keyrow * ROWB + dim * 2);                 \
            uint32_t kbh[4], kbl[4];                                            \
            ldsm4(K_HI + off, kbh);                                             \
            ldsm4(K_LO + off, kbl);                                             \
            mma16816h(S[2*np],   aqh[kg], kbh[0], kbh[1]);                      \
            mma16816h(S[2*np],   aql[kg], kbh[0], kbh[1]);                      \
            mma16816h(S[2*np],   aqh[kg], kbl[0], kbl[1]);                      \
            mma16816h(S[2*np+1], aqh[kg], kbh[2], kbh[3]);                      \
            mma16816h(S[2*np+1], aql[kg], kbh[2], kbh[3]);                      \
            mma16816h(S[2*np+1], aqh[kg], kbl[2], kbl[3]);                      \
        }                                                                       \
    }                                                                           \
} while (0)

// ---- online-max softmax + fp16 P pack + single-term PV ----
#define SM_PV(S, TI) do {                                                       \
    const int kloc0p = (t0 + (TI)) * 32;                                        \
    const int kabs   = base + kloc0p;                                           \
    const bool edge = ((TI) == 0) | ((TI) == 8) | (kabs < 0) | (kabs + 31 >= S_LEN); \
    if (edge) {                                                                 \
        _Pragma("unroll")                                                       \
        for (int j = 0; j < 4; j++) {                                           \
            _Pragma("unroll")                                                   \
            for (int r = 0; r < 4; r++) {                                       \
                int key  = kabs + 8 * j + 2 * tt + (r & 1);                     \
                int qrow = qa0 + g + ((r >> 1) << 3);                           \
                bool valid = (key >= 0) && (key < S_LEN) &&                     \
                             (key >= qrow - WIN) && (key <= qrow + WIN);        \
                if (!valid) S[j][r] = -1e30f;                                   \
            }                                                                   \
        }                                                                       \
    }                                                                           \
    float mt0 = S[0][0], mt1 = S[0][2];                                         \
    _Pragma("unroll")                                                           \
    for (int j = 0; j < 4; j++) {                                               \
        mt0 = fmaxf(mt0, fmaxf(S[j][0], S[j][1]));                              \
        mt1 = fmaxf(mt1, fmaxf(S[j][2], S[j][3]));                              \
    }                                                                           \
    mt0 = fmaxf(mt0, __shfl_xor_sync(0xffffffffu, mt0, 1));                     \
    mt0 = fmaxf(mt0, __shfl_xor_sync(0xffffffffu, mt0, 2));                     \
    mt1 = fmaxf(mt1, __shfl_xor_sync(0xffffffffu, mt1, 1));                     \
    mt1 = fmaxf(mt1, __shfl_xor_sync(0xffffffffu, mt1, 2));                     \
    float mn0 = fmaxf(mx[0], mt0), mn1 = fmaxf(mx[1], mt1);                     \
    float sc0 = __expf(mx[0] - mn0), sc1 = __expf(mx[1] - mn1);                 \
    mx[0] = mn0; mx[1] = mn1;                                                   \
    rs[0] *= sc0; rs[1] *= sc1;                                                 \
    _Pragma("unroll")                                                           \
    for (int j = 0; j < 4; j++) {                                               \
        float e0 = __expf(S[j][0] - mn0);                                       \
        float e1 = __expf(S[j][1] - mn0);                                       \
        float e2 = __expf(S[j][2] - mn1);                                       \
        float e3 = __expf(S[j][3] - mn1);                                       \
        rs[0] += e0 + e1; rs[1] += e2 + e3;                                     \
        S[j][0] = e0; S[j][1] = e1; S[j][2] = e2; S[j][3] = e3;                 \
    }                                                                           \
    _Pragma("unroll")                                                           \
    for (int j = 0; j < 8; j++) {                                               \
        of[j][0] *= sc0; of[j][1] *= sc0;                                       \
        of[j][2] *= sc1; of[j][3] *= sc1;                                       \
    }                                                                           \
    uint32_t pah[2][4];                                                         \
    _Pragma("unroll")                                                           \
    for (int kg = 0; kg < 2; kg++) {                                            \
        pah[kg][0] = pack_h(S[2*kg][0],   S[2*kg][1]);                          \
        pah[kg][1] = pack_h(S[2*kg][2],   S[2*kg][3]);                          \
        pah[kg][2] = pack_h(S[2*kg+1][0], S[2*kg+1][1]);                        \
        pah[kg][3] = pack_h(S[2*kg+1][2], S[2*kg+1][3]);                        \
    }                                                                           \
    _Pragma("unroll")                                                           \
    for (int kg = 0; kg < 2; kg++) {                                            \
        _Pragma("unroll")                                                       \
        for (int jp = 0; jp < 4; jp++) {                                        \
            int keyrow = kloc0p + kg * 16 + (mm & 1) * 8 + lm7;                 \
            int dim    = (jp * 2 + (mm >> 1)) * 8;                              \
            uint32_t off = (uint32_t)(keyrow * ROWB + dim * 2);                 \
            uint32_t vb[4];                                                     \
            ldsm4t(V_PL + off, vb);                                             \
            mma16816h(of[2*jp],   pah[kg], vb[0], vb[1]);                       \
            mma16816h(of[2*jp+1], pah[kg], vb[2], vb[3]);                       \
        }                                                                       \
    }                                                                           \
} while (0)

__global__ __launch_bounds__(256, 1)
void swa_mma_kernel(const float* __restrict__ Q, const float* __restrict__ K,
                    const float* __restrict__ V, float* __restrict__ O) {
    const int tid  = threadIdx.x;
    const int warp = tid >> 5;
    const int lane = tid & 31;
    const int g    = lane >> 2;
    const int tt   = lane & 3;
    const int mm   = lane >> 3;
    const int lm7  = lane & 7;

    const int c = blockIdx.x, h = blockIdx.y, b = blockIdx.z;
    const int cb = c * CHUNK;
    const int base = cb - WIN;

    const uint32_t SB   = (uint32_t)__cvta_generic_to_shared(sm);
    const uint32_t K_HI = SB;
    const uint32_t K_LO = SB + PLANE;
    const uint32_t V_PL = SB + 2 * PLANE;

    // ---------------- Q fragments: direct gmem -> registers (split fp16) ----------------
    uint32_t aqh[4][4], aql[4][4];
    {
        const int qrow = cb + warp * 16 + g;
        const float* qp = Q + ((size_t)(b * S_LEN + qrow) * HID) + h * DH;
        #pragma unroll
        for (int kg = 0; kg < 4; kg++) {
            const int col0 = kg * 16 + 2 * tt;
            float2 x0 = *(const float2*)(qp + col0);
            float2 x1 = *(const float2*)(qp + 8 * HID + col0);
            float2 x2 = *(const float2*)(qp + col0 + 8);
            float2 x3 = *(const float2*)(qp + 8 * HID + col0 + 8);
            split_pack_h(x0.x, x0.y, aqh[kg][0], aql[kg][0]);
            split_pack_h(x1.x, x1.y, aqh[kg][1], aql[kg][1]);
            split_pack_h(x2.x, x2.y, aqh[kg][2], aql[kg][2]);
            split_pack_h(x3.x, x3.y, aqh[kg][3], aql[kg][3]);
        }
    }

    // ---------------- Stage K (hi/lo) and V (hi only), zero-filled out of range ----------------
    {
        #pragma unroll
        for (int it = 0; it < 24; it++) {
            int j   = tid + it * 256;
            int row = j >> 4;
            int c4  = (j & 15) * 4;
            int key = base + row;
            float4 k4 = make_float4(0.f, 0.f, 0.f, 0.f), v4 = k4;
            if (key >= 0 && key < S_LEN) {
                size_t off = ((size_t)(b * S_LEN + key) * HID) + h * DH + c4;
                k4 = *(const float4*)(K + off);
                v4 = *(const float4*)(V + off);
            }
            int so = row * ROWB + c4 * 2;
            uint32_t h0, l0, h1, l1;
            split_pack_h(k4.x, k4.y, h0, l0);
            split_pack_h(k4.z, k4.w, h1, l1);
            *(uint2*)(sm + so)         = make_uint2(h0, h1);
            *(uint2*)(sm + PLANE + so) = make_uint2(l0, l1);
            *(uint2*)(sm + 2 * PLANE + so) =
                make_uint2(pack_h(v4.x, v4.y), pack_h(v4.z, v4.w));
        }
    }
    __syncthreads();

    // ---------------- Main loop: 9 tiles per warp, QK pipelined one tile ahead ----------------
    float of[8][4];
    #pragma unroll
    for (int j = 0; j < 8; j++)
        #pragma unroll
        for (int r = 0; r < 4; r++) of[j][r] = 0.f;
    float rs[2] = {0.f, 0.f};
    float mx[2] = {-60000.f, -60000.f};

    const int t0  = warp >> 1;
    const int qa0 = cb + warp * 16;

    float sA[4][4], sB[4][4];
    QK_TILE(sA, 0);
    #pragma unroll 1
    for (int ii = 0; ii < 4; ii++) {
        QK_TILE(sB, 2 * ii + 1);    // next-tile scores issue before softmax+PV of current
        SM_PV(sA, 2 * ii);
        QK_TILE(sA, 2 * ii + 2);
        SM_PV(sB, 2 * ii + 1);
    }
    SM_PV(sA, 8);

    // ---------------- Epilogue ----------------
    rs[0] += __shfl_xor_sync(0xffffffffu, rs[0], 1);
    rs[0] += __shfl_xor_sync(0xffffffffu, rs[0], 2);
    rs[1] += __shfl_xor_sync(0xffffffffu, rs[1], 1);
    rs[1] += __shfl_xor_sync(0xffffffffu, rs[1], 2);
    const float inv_lo = 1.f / rs[0];
    const float inv_hi = 1.f / rs[1];

    const int q_lo = qa0 + g;
    const int q_hi = q_lo + 8;
    #pragma unroll
    for (int j = 0; j < 8; j++) {
        int col = h * DH + 8 * j + 2 * tt;
        size_t off_lo = ((size_t)(b * S_LEN + q_lo) * HID) + col;
        size_t off_hi = ((size_t)(b * S_LEN + q_hi) * HID) + col;
        *(float2*)(O + off_lo) = make_float2(of[j][0] * inv_lo, of[j][1] * inv_lo);
        *(float2*)(O + off_hi) = make_float2(of[j][2] * inv_hi, of[j][3] * inv_hi);
    }
}

extern "C" void kernel_launch(void* const* d_in, const int* in_sizes, int n_in,
                              void* d_out, int out_size) {
    (void)n_in; (void)out_size;
    const float* Q = (const float*)d_in[0];
    const float* K = (const float*)d_in[1];
    const float* V = (const float*)d_in[2];
    float* O = (float*)d_out;

    int B = in_sizes[0] / (S_LEN * HID);
    cudaFuncSetAttribute(swa_mma_kernel,
                         cudaFuncAttributeMaxDynamicSharedMemorySize, SMEM_TOTAL);
    dim3 grid(S_LEN / CHUNK, NH, B);
    swa_mma_kernel<<<grid, 256, SMEM_TOTAL>>>(Q, K, V, O);
}